// round 1
// baseline (speedup 1.0000x reference)
#include <cuda_runtime.h>
#include <math.h>

#define D    512
#define BLKR 64
#define NB   128        // batch
#define M    6304       // memory contexts
#define TOPK 50
#define CEPS 1e-8f

// ---------------- scratch (static device globals; no allocation) ----------------
__device__ float g_minv[M];
__device__ float g_qinv[NB];
__device__ float g_cos[(size_t)NB * M];
__device__ int   g_tidx[NB * TOPK];
__device__ float g_tw[NB * TOPK];

// ---------------- 1) row inverse norms (mc rows then q rows) ----------------
__global__ void norms_kernel(const float* __restrict__ q, const float* __restrict__ mc) {
    int r = blockIdx.x;
    const float* src = (r < M) ? (mc + (size_t)r * D) : (q + (size_t)(r - M) * D);
    int t = threadIdx.x;                       // 128 threads, 1 float4 each
    float4 v = ((const float4*)src)[t];
    float ss = v.x * v.x + v.y * v.y + v.z * v.z + v.w * v.w;
#pragma unroll
    for (int o = 16; o > 0; o >>= 1) ss += __shfl_xor_sync(0xffffffffu, ss, o);
    __shared__ float s[4];
    if ((t & 31) == 0) s[t >> 5] = ss;
    __syncthreads();
    if (t == 0) {
        float tot = s[0] + s[1] + s[2] + s[3];
        float inv = 1.0f / fmaxf(sqrtf(tot), CEPS);
        if (r < M) g_minv[r] = inv;
        else       g_qinv[r - M] = inv;
    }
}

// ---------------- 2) cos = (q/|q|) @ (mc/|mc|)^T, fp32 tiled GEMM ----------------
// BM=128 (all of B), BN=32, BK=32. 197 blocks (197*32 == 6304, no edge guards).
#define GBN 32
#define GBK 32
__global__ __launch_bounds__(256) void cos_gemm_kernel(const float* __restrict__ q,
                                                       const float* __restrict__ mc) {
    __shared__ float As[GBK][NB];   // 16 KB, k-major
    __shared__ float Bs[GBK][GBN];  // 4 KB,  k-major
    int t  = threadIdx.x;
    int tx = t & 15;                // 16 -> 32 cols, 2 per thread
    int ty = t >> 4;                // 16 -> 128 rows, 8 per thread
    int m0 = blockIdx.x * GBN;

    float acc[8][2] = {};

    for (int k0 = 0; k0 < D; k0 += GBK) {
        // load A tile (q): 128x32 floats, 4 float4 per thread, store transposed
#pragma unroll
        for (int i = 0; i < 4; i++) {
            int lin = t + i * 256;
            int row = lin >> 3, c4 = lin & 7;
            float4 v = *(const float4*)(q + (size_t)row * D + k0 + c4 * 4);
            As[c4 * 4 + 0][row] = v.x;
            As[c4 * 4 + 1][row] = v.y;
            As[c4 * 4 + 2][row] = v.z;
            As[c4 * 4 + 3][row] = v.w;
        }
        // load B tile (mc): 32x32 floats, 1 float4 per thread
        {
            int row = t >> 3, c4 = t & 7;
            float4 v = *(const float4*)(mc + (size_t)(m0 + row) * D + k0 + c4 * 4);
            Bs[c4 * 4 + 0][row] = v.x;
            Bs[c4 * 4 + 1][row] = v.y;
            Bs[c4 * 4 + 2][row] = v.z;
            Bs[c4 * 4 + 3][row] = v.w;
        }
        __syncthreads();
#pragma unroll
        for (int k = 0; k < GBK; k++) {
            float4 a0 = ((const float4*)&As[k][0])[ty * 2];
            float4 a1 = ((const float4*)&As[k][0])[ty * 2 + 1];
            float2 bv = ((const float2*)&Bs[k][0])[tx];
            float av[8] = {a0.x, a0.y, a0.z, a0.w, a1.x, a1.y, a1.z, a1.w};
#pragma unroll
            for (int i = 0; i < 8; i++) {
                acc[i][0] += av[i] * bv.x;
                acc[i][1] += av[i] * bv.y;
            }
        }
        __syncthreads();
    }
#pragma unroll
    for (int i = 0; i < 8; i++) {
        int br = ty * 8 + i;
        float qi = g_qinv[br];
#pragma unroll
        for (int j = 0; j < 2; j++) {
            int m = m0 + tx * 2 + j;
            g_cos[(size_t)br * M + m] = acc[i][j] * qi * g_minv[m];
        }
    }
}

// ---------------- 3) per-row top-50 (iterative argmax, jax tie = lowest idx) + softmax ----
__global__ __launch_bounds__(256) void topk_kernel() {
    __shared__ float row[M];        // 25216 B
    __shared__ float s_val[256];
    __shared__ int   s_idx[256];
    __shared__ float s_top[TOPK];
    int b = blockIdx.x, t = threadIdx.x;

    for (int i = t; i < M; i += 256) row[i] = g_cos[(size_t)b * M + i];
    __syncthreads();

    for (int kk = 0; kk < TOPK; kk++) {
        float bv = -3.4e38f;
        int bi = 0x7fffffff;
        for (int i = t; i < M; i += 256) {
            float v = row[i];
            if (v > bv || (v == bv && i < bi)) { bv = v; bi = i; }
        }
        s_val[t] = bv; s_idx[t] = bi;
        __syncthreads();
        for (int s = 128; s > 0; s >>= 1) {
            if (t < s) {
                float ov = s_val[t + s];
                int   oi = s_idx[t + s];
                if (ov > s_val[t] || (ov == s_val[t] && oi < s_idx[t])) {
                    s_val[t] = ov; s_idx[t] = oi;
                }
            }
            __syncthreads();
        }
        if (t == 0) {
            int wi = s_idx[0];
            s_top[kk] = s_val[0];
            g_tidx[b * TOPK + kk] = wi;
            row[wi] = -3.4e38f;
        }
        __syncthreads();
    }

    if (t == 0) {
        float mx = s_top[0];          // picked in descending order -> first is max
        float e[TOPK];
        float sum = 0.f;
        for (int kk = 0; kk < TOPK; kk++) { e[kk] = expf(s_top[kk] - mx); sum += e[kk]; }
        float inv = 1.f / sum;
        for (int kk = 0; kk < TOPK; kk++) g_tw[b * TOPK + kk] = e[kk] * inv;
    }
}

// ---------------- 4) weighted block gather + blend (HBM-bound) ----------------
__global__ __launch_bounds__(128) void gather_kernel(const float* __restrict__ enc,
                                                     const float* __restrict__ fp,
                                                     const float* __restrict__ weight,
                                                     float* __restrict__ out) {
    __shared__ int   s_i[TOPK];
    __shared__ float s_w[TOPK];
    int b = blockIdx.x >> 6;
    int l = blockIdx.x & 63;
    int t = threadIdx.x;                       // 128 threads x float4 = 512 floats
    if (t < TOPK) {
        s_i[t] = g_tidx[b * TOPK + t];
        s_w[t] = g_tw[b * TOPK + t];
    }
    __syncthreads();

    float ax = 0.f, ay = 0.f, az = 0.f, aw = 0.f;
#pragma unroll 5
    for (int kk = 0; kk < TOPK; kk++) {
        const float4* src = (const float4*)(fp + ((size_t)s_i[kk] * BLKR + l) * D);
        float4 v = src[t];
        float w = s_w[kk];
        ax += w * v.x; ay += w * v.y; az += w * v.z; aw += w * v.w;
    }

    float wm = weight[0];
    float em = 1.f - wm;
    size_t off = ((size_t)b * BLKR + l) * D;
    float4 e = ((const float4*)(enc + off))[t];
    float4 o;
    o.x = ax * wm + e.x * em;
    o.y = ay * wm + e.y * em;
    o.z = az * wm + e.z * em;
    o.w = aw * wm + e.w * em;
    ((float4*)(out + off))[t] = o;
}

// ---------------- launch ----------------
extern "C" void kernel_launch(void* const* d_in, const int* in_sizes, int n_in,
                              void* d_out, int out_size) {
    const float* enc = (const float*)d_in[0];   // [128, 64, 512]
    const float* q   = (const float*)d_in[1];   // [128, 512]
    const float* mc  = (const float*)d_in[2];   // [6304, 512]
    const float* fp  = (const float*)d_in[3];   // [403456, 512]
    const float* w   = (const float*)d_in[4];   // [1]
    float* out = (float*)d_out;                 // [128, 64, 512]

    norms_kernel<<<M + NB, 128>>>(q, mc);
    cos_gemm_kernel<<<M / GBN, 256>>>(q, mc);
    topk_kernel<<<NB, 256>>>();
    gather_kernel<<<NB * BLKR, 128>>>(enc, fp, w, out);
}

// round 2
// speedup vs baseline: 1.4624x; 1.4624x over previous
#include <cuda_runtime.h>
#include <math.h>
#include <stdint.h>

#define D    512
#define BLKR 64
#define NB   128        // batch
#define M    6304       // memory contexts
#define TOPK 50
#define CEPS 1e-8f
#define KSPLIT 2

// ---------------- scratch ----------------
__device__ float g_minv[M];
__device__ float g_qinv[NB];
__device__ float g_cosp[KSPLIT][(size_t)NB * M];
__device__ int   g_tidx[NB * TOPK];
__device__ float g_tw[NB * TOPK];

// ---------------- 1) row inverse norms ----------------
__global__ void norms_kernel(const float* __restrict__ q, const float* __restrict__ mc) {
    int r = blockIdx.x;
    const float* src = (r < M) ? (mc + (size_t)r * D) : (q + (size_t)(r - M) * D);
    int t = threadIdx.x;                       // 128 threads, 1 float4 each
    float4 v = ((const float4*)src)[t];
    float ss = v.x * v.x + v.y * v.y + v.z * v.z + v.w * v.w;
#pragma unroll
    for (int o = 16; o > 0; o >>= 1) ss += __shfl_xor_sync(0xffffffffu, ss, o);
    __shared__ float s[4];
    if ((t & 31) == 0) s[t >> 5] = ss;
    __syncthreads();
    if (t == 0) {
        float tot = s[0] + s[1] + s[2] + s[3];
        float inv = 1.0f / fmaxf(sqrtf(tot), CEPS);
        if (r < M) g_minv[r] = inv;
        else       g_qinv[r - M] = inv;
    }
}

// ---------------- 2) dot = q @ mc^T via packed f32x2 FMA, split-K ----------------
// BM=128 (all of B), BN=32, BK=32, K split in 2 halves of 256.
// 128 threads: 16(ty: 8 rows) x 8(tx: 4 cols). Accumulate k-pairs in f32x2.
#define GBN 32
#define GBK 32
#define APAD 36

__device__ __forceinline__ void ffma2(unsigned long long &d,
                                      unsigned long long a,
                                      unsigned long long b) {
    asm("fma.rn.f32x2 %0, %1, %2, %0;" : "+l"(d) : "l"(a), "l"(b));
}

__global__ __launch_bounds__(128) void cos_gemm_kernel(const float* __restrict__ q,
                                                       const float* __restrict__ mc) {
    __shared__ float As[NB][APAD];    // [row][k], 18KB
    __shared__ float Bs[GBN][APAD];   // [row][k], 4.5KB
    int t  = threadIdx.x;
    int tx = t & 7;                   // col group: cols tx*4 .. +3
    int ty = t >> 3;                  // row group: rows ty*8 .. +7
    int m0 = blockIdx.x * GBN;
    int kz = blockIdx.y;
    int kbase = kz * (D / KSPLIT);

    unsigned long long acc[8][4];
#pragma unroll
    for (int i = 0; i < 8; i++)
#pragma unroll
        for (int j = 0; j < 4; j++) acc[i][j] = 0ull;

    for (int kt = 0; kt < (D / KSPLIT); kt += GBK) {
        int k0 = kbase + kt;
        // A tile: 128x32 floats = 1024 float4, 8 per thread
#pragma unroll
        for (int i = 0; i < 8; i++) {
            int lin = t + i * 128;
            int row = lin >> 3, c4 = lin & 7;
            float4 v = *(const float4*)(q + (size_t)row * D + k0 + c4 * 4);
            *(float4*)&As[row][c4 * 4] = v;
        }
        // B tile: 32x32 floats = 256 float4, 2 per thread
#pragma unroll
        for (int i = 0; i < 2; i++) {
            int lin = t + i * 128;
            int row = lin >> 3, c4 = lin & 7;
            float4 v = *(const float4*)(mc + (size_t)(m0 + row) * D + k0 + c4 * 4);
            *(float4*)&Bs[row][c4 * 4] = v;
        }
        __syncthreads();
#pragma unroll
        for (int k4 = 0; k4 < GBK / 4; k4++) {
            float4 bf[4];
#pragma unroll
            for (int j = 0; j < 4; j++) bf[j] = *(const float4*)&Bs[tx * 4 + j][k4 * 4];
            float4 af[8];
#pragma unroll
            for (int i = 0; i < 8; i++) af[i] = *(const float4*)&As[ty * 8 + i][k4 * 4];
#pragma unroll
            for (int i = 0; i < 8; i++) {
                const unsigned long long* ap = (const unsigned long long*)&af[i];
#pragma unroll
                for (int j = 0; j < 4; j++) {
                    const unsigned long long* bp = (const unsigned long long*)&bf[j];
                    ffma2(acc[i][j], ap[0], bp[0]);
                    ffma2(acc[i][j], ap[1], bp[1]);
                }
            }
        }
        __syncthreads();
    }
#pragma unroll
    for (int i = 0; i < 8; i++) {
        int br = ty * 8 + i;
#pragma unroll
        for (int j = 0; j < 4; j++) {
            unsigned long long a = acc[i][j];
            float lo = __uint_as_float((unsigned)(a & 0xffffffffu));
            float hi = __uint_as_float((unsigned)(a >> 32));
            g_cosp[kz][(size_t)br * M + m0 + tx * 4 + j] = lo + hi;
        }
    }
}

// ---------------- 3) radix-select top-50 + softmax ----------------
// Per batch row: exact 50th-key threshold via 4x 8-bit MSB radix passes on
// order-flipped uint keys; ties resolved by lowest index (jax semantics).
#define TIECAP 256

__device__ __forceinline__ unsigned key_of(float v) {
    unsigned u = __float_as_uint(v);
    return (u & 0x80000000u) ? ~u : (u | 0x80000000u);   // monotonic flip
}
__device__ __forceinline__ float val_of(unsigned k) {
    unsigned u = (k & 0x80000000u) ? (k & 0x7fffffffu) : ~k;
    return __uint_as_float(u);
}

__global__ __launch_bounds__(256) void topk_kernel() {
    __shared__ unsigned keys[M];            // 25.2 KB
    __shared__ int hist[256];
    __shared__ unsigned s_prefix;
    __shared__ int s_remaining;
    __shared__ int s_gtcnt, s_tiecnt;
    __shared__ unsigned gt_k[64];
    __shared__ int gt_i[64];
    __shared__ int tie_i[TIECAP];
    __shared__ int fin_idx[TOPK];
    __shared__ float fin_val[TOPK];
    __shared__ float fin_e[TOPK];
    __shared__ float s_sum;

    int b = blockIdx.x, t = threadIdx.x;
    float qi = g_qinv[b];
    const float* p0 = &g_cosp[0][(size_t)b * M];
    const float* p1 = &g_cosp[1][(size_t)b * M];

    for (int i = t; i < M; i += 256)
        keys[i] = key_of((p0[i] + p1[i]) * qi * g_minv[i]);
    if (t == 0) { s_prefix = 0u; s_remaining = TOPK; s_gtcnt = 0; s_tiecnt = 0; }
    __syncthreads();

#pragma unroll
    for (int level = 0; level < 4; level++) {
        int shift = 24 - level * 8;
        if (t < 256) hist[t] = 0;
        __syncthreads();
        unsigned pfx = s_prefix;
        for (int i = t; i < M; i += 256) {
            unsigned k = keys[i];
            bool in = (level == 0) || ((k >> (shift + 8)) == pfx);
            if (in) atomicAdd(&hist[(k >> shift) & 255], 1);
        }
        __syncthreads();
        if (t == 0) {
            int rem = s_remaining, cum = 0, td = 0;
            for (int d = 255; d >= 0; d--) {
                int h = hist[d];
                if (cum + h >= rem) { td = d; break; }
                cum += h;
            }
            s_prefix = (s_prefix << 8) | (unsigned)td;
            s_remaining = rem - cum;      // picks needed within digit==td
        }
        __syncthreads();
    }

    unsigned T = s_prefix;               // exact 50th-largest key (with ties)
    int rem = s_remaining;               // how many of the ==T ties to take
    // collect
    for (int i = t; i < M; i += 256) {
        unsigned k = keys[i];
        if (k > T) {
            int p = atomicAdd(&s_gtcnt, 1);
            gt_k[p] = k; gt_i[p] = i;
        } else if (k == T) {
            int p = atomicAdd(&s_tiecnt, 1);
            if (p < TIECAP) tie_i[p] = i;
        }
    }
    __syncthreads();
    int ngt = s_gtcnt;                   // == TOPK - rem
    int ntie = min(s_tiecnt, TIECAP);
    // rank gt elements by (key desc, idx asc)
    if (t < ngt) {
        unsigned mk = gt_k[t]; int mi = gt_i[t];
        int rank = 0;
        for (int j = 0; j < ngt; j++) {
            unsigned ok = gt_k[j]; int oi = gt_i[j];
            if (ok > mk || (ok == mk && oi < mi)) rank++;
        }
        fin_idx[rank] = mi;
        fin_val[rank] = val_of(mk);
    }
    // ties: take `rem` lowest indices, placed after all gt
    if (t < ntie) {
        int mi = tie_i[t];
        int rank = 0;
        for (int j = 0; j < ntie; j++) if (tie_i[j] < mi) rank++;
        if (rank < rem) {
            fin_idx[ngt + rank] = mi;
            fin_val[ngt + rank] = val_of(T);
        }
    }
    __syncthreads();
    // softmax over fin_val (descending => fin_val[0] is max)
    if (t < TOPK) fin_e[t] = expf(fin_val[t] - fin_val[0]);
    __syncthreads();
    if (t == 0) {
        float s = 0.f;
        for (int kk = 0; kk < TOPK; kk++) s += fin_e[kk];
        s_sum = 1.0f / s;
    }
    __syncthreads();
    if (t < TOPK) {
        g_tidx[b * TOPK + t] = fin_idx[t];
        g_tw[b * TOPK + t]   = fin_e[t] * s_sum;
    }
}

// ---------------- 4) weighted block gather + blend (l-major for L2 reuse) ----
__global__ __launch_bounds__(128) void gather_kernel(const float* __restrict__ enc,
                                                     const float* __restrict__ fp,
                                                     const float* __restrict__ weight,
                                                     float* __restrict__ out) {
    __shared__ int   s_i[TOPK];
    __shared__ float s_w[TOPK];
    int b = blockIdx.x & (NB - 1);     // fast dim: batch  -> concurrent CTAs share l
    int l = blockIdx.x >> 7;           // slow dim: row within block
    int t = threadIdx.x;               // 128 threads x float4 = 512 floats
    if (t < TOPK) {
        s_i[t] = g_tidx[b * TOPK + t];
        s_w[t] = g_tw[b * TOPK + t];
    }
    __syncthreads();

    float ax = 0.f, ay = 0.f, az = 0.f, aw = 0.f;
#pragma unroll 5
    for (int kk = 0; kk < TOPK; kk++) {
        const float4* src = (const float4*)(fp + ((size_t)s_i[kk] * BLKR + l) * D);
        float4 v = src[t];
        float w = s_w[kk];
        ax += w * v.x; ay += w * v.y; az += w * v.z; aw += w * v.w;
    }

    float wm = weight[0];
    float em = 1.f - wm;
    size_t off = ((size_t)b * BLKR + l) * D;
    float4 e = ((const float4*)(enc + off))[t];
    float4 o;
    o.x = ax * wm + e.x * em;
    o.y = ay * wm + e.y * em;
    o.z = az * wm + e.z * em;
    o.w = aw * wm + e.w * em;
    ((float4*)(out + off))[t] = o;
}

// ---------------- launch ----------------
extern "C" void kernel_launch(void* const* d_in, const int* in_sizes, int n_in,
                              void* d_out, int out_size) {
    const float* enc = (const float*)d_in[0];   // [128, 64, 512]
    const float* q   = (const float*)d_in[1];   // [128, 512]
    const float* mc  = (const float*)d_in[2];   // [6304, 512]
    const float* fp  = (const float*)d_in[3];   // [403456, 512]
    const float* w   = (const float*)d_in[4];   // [1]
    float* out = (float*)d_out;                 // [128, 64, 512]

    norms_kernel<<<M + NB, 128>>>(q, mc);
    cos_gemm_kernel<<<dim3(M / GBN, KSPLIT), 128>>>(q, mc);
    topk_kernel<<<NB, 256>>>();
    gather_kernel<<<NB * BLKR, 128>>>(enc, fp, w, out);
}

// round 5
// speedup vs baseline: 1.7918x; 1.2252x over previous
#include <cuda_runtime.h>
#include <math.h>
#include <stdint.h>

#define D    512
#define BLKR 64
#define NB   128        // batch
#define M    6304       // memory contexts
#define TOPK 50
#define CEPS 1e-8f
#define KSPLIT 4

// ---------------- scratch ----------------
__device__ float g_minv[M];
__device__ float g_qinv[NB];
__device__ float g_cosp[KSPLIT][(size_t)NB * M];
__device__ int   g_tidx[NB * TOPK];
__device__ float g_tw[NB * TOPK];

// ---------------- 1) row inverse norms ----------------
__global__ void norms_kernel(const float* __restrict__ q, const float* __restrict__ mc) {
    int r = blockIdx.x;
    const float* src = (r < M) ? (mc + (size_t)r * D) : (q + (size_t)(r - M) * D);
    int t = threadIdx.x;                       // 128 threads, 1 float4 each
    float4 v = ((const float4*)src)[t];
    float ss = v.x * v.x + v.y * v.y + v.z * v.z + v.w * v.w;
#pragma unroll
    for (int o = 16; o > 0; o >>= 1) ss += __shfl_xor_sync(0xffffffffu, ss, o);
    __shared__ float s[4];
    if ((t & 31) == 0) s[t >> 5] = ss;
    __syncthreads();
    if (t == 0) {
        float tot = s[0] + s[1] + s[2] + s[3];
        float inv = 1.0f / fmaxf(sqrtf(tot), CEPS);
        if (r < M) g_minv[r] = inv;
        else       g_qinv[r - M] = inv;
    }
}

// ---------------- 2) dot = q @ mc^T, packed f32x2 FMA, split-K=4 ----------------
// BM=128, BN=32, BK=32. 256 threads; thread tile 4x4 (rows ty+32i, cols tx+8j).
#define GBN 32
#define GBK 32
#define APAD 36

__device__ __forceinline__ void ffma2(unsigned long long &d,
                                      unsigned long long a,
                                      unsigned long long b) {
    asm("fma.rn.f32x2 %0, %1, %2, %0;" : "+l"(d) : "l"(a), "l"(b));
}

__global__ __launch_bounds__(256) void cos_gemm_kernel(const float* __restrict__ q,
                                                       const float* __restrict__ mc) {
    __shared__ float As[NB][APAD];    // 18 KB
    __shared__ float Bs[GBN][APAD];   // 4.5 KB
    int t  = threadIdx.x;
    int tx = t & 7;                   // cols tx + 8j
    int ty = t >> 3;                  // rows ty + 32i  (ty in 0..31)
    int m0 = blockIdx.x * GBN;
    int kbase = blockIdx.y * (D / KSPLIT);

    unsigned long long acc[4][4];
#pragma unroll
    for (int i = 0; i < 4; i++)
#pragma unroll
        for (int j = 0; j < 4; j++) acc[i][j] = 0ull;

    for (int kt = 0; kt < (D / KSPLIT); kt += GBK) {
        int k0 = kbase + kt;
        // A tile: 128x32 floats = 1024 float4, 4 per thread
#pragma unroll
        for (int i = 0; i < 4; i++) {
            int lin = t + i * 256;
            int row = lin >> 3, c4 = lin & 7;
            float4 v = *(const float4*)(q + (size_t)row * D + k0 + c4 * 4);
            *(float4*)&As[row][c4 * 4] = v;
        }
        // B tile: 32x32 floats = 256 float4, 1 per thread
        {
            int row = t >> 3, c4 = t & 7;
            float4 v = *(const float4*)(mc + (size_t)(m0 + row) * D + k0 + c4 * 4);
            *(float4*)&Bs[row][c4 * 4] = v;
        }
        __syncthreads();
#pragma unroll
        for (int k4 = 0; k4 < GBK / 4; k4++) {
            float4 bf[4];
#pragma unroll
            for (int j = 0; j < 4; j++) bf[j] = *(const float4*)&Bs[tx + 8 * j][k4 * 4];
            float4 af[4];
#pragma unroll
            for (int i = 0; i < 4; i++) af[i] = *(const float4*)&As[ty + 32 * i][k4 * 4];
#pragma unroll
            for (int i = 0; i < 4; i++) {
                const unsigned long long* ap = (const unsigned long long*)&af[i];
#pragma unroll
                for (int j = 0; j < 4; j++) {
                    const unsigned long long* bp = (const unsigned long long*)&bf[j];
                    ffma2(acc[i][j], ap[0], bp[0]);
                    ffma2(acc[i][j], ap[1], bp[1]);
                }
            }
        }
        __syncthreads();
    }
    float* dst = &g_cosp[blockIdx.y][0];
#pragma unroll
    for (int i = 0; i < 4; i++) {
        int br = ty + 32 * i;
#pragma unroll
        for (int j = 0; j < 4; j++) {
            unsigned long long a = acc[i][j];
            float lo = __uint_as_float((unsigned)(a & 0xffffffffu));
            float hi = __uint_as_float((unsigned)(a >> 32));
            dst[(size_t)br * M + m0 + tx + 8 * j] = lo + hi;
        }
    }
}

// ---------------- 3) radix-select top-50 + softmax ----------------
#define TIECAP 256

__device__ __forceinline__ unsigned key_of(float v) {
    unsigned u = __float_as_uint(v);
    return (u & 0x80000000u) ? ~u : (u | 0x80000000u);   // monotonic flip
}
__device__ __forceinline__ float val_of(unsigned k) {
    unsigned u = (k & 0x80000000u) ? (k & 0x7fffffffu) : ~k;
    return __uint_as_float(u);
}

__global__ __launch_bounds__(256) void topk_kernel() {
    __shared__ unsigned keys[M];            // 25.2 KB
    __shared__ int suf[257];                // suffix counts (suf[256]=0)
    __shared__ unsigned s_prefix;
    __shared__ int s_remaining;
    __shared__ int s_gtcnt, s_tiecnt;
    __shared__ unsigned gt_k[64];
    __shared__ int gt_i[64];
    __shared__ int tie_i[TIECAP];
    __shared__ int fin_idx[TOPK];
    __shared__ float fin_val[TOPK];
    __shared__ float fin_e[TOPK];
    __shared__ float s_sum;

    int b = blockIdx.x, t = threadIdx.x;
    float qi = g_qinv[b];
    const float* p0 = &g_cosp[0][(size_t)b * M];
    const float* p1 = &g_cosp[1][(size_t)b * M];
    const float* p2 = &g_cosp[2][(size_t)b * M];
    const float* p3 = &g_cosp[3][(size_t)b * M];

    for (int i = t; i < M; i += 256) {
        float v = ((p0[i] + p1[i]) + (p2[i] + p3[i])) * qi * g_minv[i];
        keys[i] = key_of(v);
    }
    if (t == 0) { s_prefix = 0u; s_remaining = TOPK; s_gtcnt = 0; s_tiecnt = 0; }
    __syncthreads();

#pragma unroll
    for (int level = 0; level < 4; level++) {
        int shift = 24 - level * 8;
        suf[t] = 0;
        if (t == 0) suf[256] = 0;
        __syncthreads();
        unsigned pfx = s_prefix;
        for (int i = t; i < M; i += 256) {
            unsigned k = keys[i];
            bool in = (level == 0) || ((k >> (shift + 8)) == pfx);
            if (in) atomicAdd(&suf[(k >> shift) & 255], 1);
        }
        __syncthreads();
        // parallel suffix sum: suf[d] = count of digits >= d
#pragma unroll
        for (int s = 1; s < 256; s <<= 1) {
            int add = (t + s < 256) ? suf[t + s] : 0;
            __syncthreads();
            suf[t] += add;
            __syncthreads();
        }
        int rem = s_remaining;
        // threshold digit: largest d with suf[d] >= rem
        if (suf[t] >= rem && suf[t + 1] < rem) {
            s_prefix = (s_prefix << 8) | (unsigned)t;
            s_remaining = rem - suf[t + 1];
        }
        __syncthreads();
    }

    unsigned T = s_prefix;               // exact 50th-largest key
    int rem = s_remaining;
    for (int i = t; i < M; i += 256) {
        unsigned k = keys[i];
        if (k > T) {
            int p = atomicAdd(&s_gtcnt, 1);
            gt_k[p] = k; gt_i[p] = i;
        } else if (k == T) {
            int p = atomicAdd(&s_tiecnt, 1);
            if (p < TIECAP) tie_i[p] = i;
        }
    }
    __syncthreads();
    int ngt = s_gtcnt;                   // == TOPK - rem
    int ntie = min(s_tiecnt, TIECAP);
    if (t < ngt) {
        unsigned mk = gt_k[t]; int mi = gt_i[t];
        int rank = 0;
        for (int j = 0; j < ngt; j++) {
            unsigned ok = gt_k[j]; int oi = gt_i[j];
            if (ok > mk || (ok == mk && oi < mi)) rank++;
        }
        fin_idx[rank] = mi;
        fin_val[rank] = val_of(mk);
    }
    if (t < ntie) {
        int mi = tie_i[t];
        int rank = 0;
        for (int j = 0; j < ntie; j++) if (tie_i[j] < mi) rank++;
        if (rank < rem) {
            fin_idx[ngt + rank] = mi;
            fin_val[ngt + rank] = val_of(T);
        }
    }
    __syncthreads();
    if (t < TOPK) fin_e[t] = expf(fin_val[t] - fin_val[0]);
    __syncthreads();
    if (t == 0) {
        float s = 0.f;
        for (int kk = 0; kk < TOPK; kk++) s += fin_e[kk];
        s_sum = 1.0f / s;
    }
    __syncthreads();
    if (t < TOPK) {
        g_tidx[b * TOPK + t] = fin_idx[t];
        g_tw[b * TOPK + t]   = fin_e[t] * s_sum;
    }
}

// ---------------- 4) weighted block gather + blend (l-major, MLP batched) ----
__global__ __launch_bounds__(128) void gather_kernel(const float* __restrict__ enc,
                                                     const float* __restrict__ fp,
                                                     const float* __restrict__ weight,
                                                     float* __restrict__ out) {
    __shared__ const float4* s_p[TOPK];
    __shared__ float s_w[TOPK];
    int b = blockIdx.x & (NB - 1);     // fast dim: batch -> concurrent CTAs share l
    int l = blockIdx.x >> 7;           // slow dim: row within block
    int t = threadIdx.x;               // 128 threads x float4 = 512 floats
    if (t < TOPK) {
        s_p[t] = (const float4*)(fp + ((size_t)g_tidx[b * TOPK + t] * BLKR + l) * D);
        s_w[t] = g_tw[b * TOPK + t];
    }
    __syncthreads();

    float ax = 0.f, ay = 0.f, az = 0.f, aw = 0.f;
#pragma unroll
    for (int kk = 0; kk < TOPK; kk += 10) {
        float4 v[10];
#pragma unroll
        for (int u = 0; u < 10; u++) v[u] = s_p[kk + u][t];
#pragma unroll
        for (int u = 0; u < 10; u++) {
            float w = s_w[kk + u];
            ax += w * v[u].x; ay += w * v[u].y; az += w * v[u].z; aw += w * v[u].w;
        }
    }

    float wm = weight[0];
    float em = 1.f - wm;
    size_t off = ((size_t)b * BLKR + l) * D;
    float4 e = ((const float4*)(enc + off))[t];
    float4 o;
    o.x = ax * wm + e.x * em;
    o.y = ay * wm + e.y * em;
    o.z = az * wm + e.z * em;
    o.w = aw * wm + e.w * em;
    ((float4*)(out + off))[t] = o;
}

// ---------------- launch ----------------
extern "C" void kernel_launch(void* const* d_in, const int* in_sizes, int n_in,
                              void* d_out, int out_size) {
    const float* enc = (const float*)d_in[0];   // [128, 64, 512]
    const float* q   = (const float*)d_in[1];   // [128, 512]
    const float* mc  = (const float*)d_in[2];   // [6304, 512]
    const float* fp  = (const float*)d_in[3];   // [403456, 512]
    const float* w   = (const float*)d_in[4];   // [1]
    float* out = (float*)d_out;                 // [128, 64, 512]

    norms_kernel<<<M + NB, 128>>>(q, mc);
    cos_gemm_kernel<<<dim3(M / GBN, KSPLIT), 256>>>(q, mc);
    topk_kernel<<<NB, 256>>>();
    gather_kernel<<<NB * BLKR, 128>>>(enc, fp, w, out);
}